// round 2
// baseline (speedup 1.0000x reference)
#include <cuda_runtime.h>
#include <cuda_bf16.h>
#include <cstdint>

#define BATCH   16
#define C_DIM   256
#define HDIM    32
#define WDIM    32
#define N_ROWS  16384
#define K_CB    8192
#define Z_ELEMS 4194304
#define OUT_LOSS_OFF 4194304
#define OUT_IDX_OFF  4194305

#define CAP     32           // candidate list capacity per row
#define MARGIN_EZ 3e-4f      // screen margin in ez units (worst-case-safe)

// ---- static device scratch ----
__device__ __align__(16) __nv_bfloat16 g_zb[N_ROWS * C_DIM];   // A in bf16 [N][C]
__device__ __align__(16) __nv_bfloat16 g_cbb[K_CB * C_DIM];    // B in bf16 [K][C]
__device__ float  g_z2[N_ROWS];
__device__ float  g_e2[K_CB];
__device__ int    g_cnt[N_ROWS];
__device__ int    g_cand[N_ROWS * CAP];
__device__ int    g_bestidx[N_ROWS];
__device__ double g_losspart[16384];

// ---------------------------------------------------------------------------
// converts
// ---------------------------------------------------------------------------
__global__ void convert_z_kernel(const float* __restrict__ z) {
    int t = blockIdx.x * 256 + threadIdx.x;          // coalesced read mapping
    int r = t & 1023;
    int c = (t >> 10) & 255;
    int b = t >> 18;
    float v = z[(size_t)b * 262144 + (size_t)c * 1024 + r];
    g_zb[(size_t)(b * 1024 + r) * 256 + c] = __float2bfloat16(v);
}
__global__ void convert_cb_kernel(const float* __restrict__ cb) {
    int t = blockIdx.x * 256 + threadIdx.x;
    g_cbb[t] = __float2bfloat16(cb[t]);
}

// ---------------------------------------------------------------------------
// z2 / e2 (fp32, same as R1)
// ---------------------------------------------------------------------------
__global__ void z2_kernel(const float* __restrict__ z) {
    int warp = (blockIdx.x * blockDim.x + threadIdx.x) >> 5;
    int lane = threadIdx.x & 31;
    if (warp >= N_ROWS) return;
    int b = warp >> 10;
    int r = warp & 1023;
    const float* p = z + (size_t)b * 262144 + r;
    float s = 0.0f;
#pragma unroll
    for (int t = 0; t < 8; ++t) { float v = p[(size_t)(lane + 32 * t) * 1024]; s = fmaf(v, v, s); }
#pragma unroll
    for (int o = 16; o > 0; o >>= 1) s += __shfl_xor_sync(0xffffffffu, s, o);
    if (lane == 0) g_z2[warp] = s;
}
__global__ void e2_kernel(const float* __restrict__ cb) {
    int warp = (blockIdx.x * blockDim.x + threadIdx.x) >> 5;
    int lane = threadIdx.x & 31;
    if (warp >= K_CB) return;
    const float* p = cb + (size_t)warp * C_DIM;
    float s = 0.0f;
#pragma unroll
    for (int t = 0; t < 8; ++t) { float v = p[lane + 32 * t]; s = fmaf(v, v, s); }
#pragma unroll
    for (int o = 16; o > 0; o >>= 1) s += __shfl_xor_sync(0xffffffffu, s, o);
    if (lane == 0) g_e2[warp] = s;
}

// ---------------------------------------------------------------------------
// bf16 tensor-core screen: per 128-row block, loop all 64 candidate tiles.
// Tracks per-row running max(ez~); appends candidates within MARGIN of it.
// ---------------------------------------------------------------------------
#define A_STRIDE_B 528                    // (256+8) bf16 = 528 bytes (ldmatrix conflict-free)
#define SM_A_OFF   0
#define SM_B_OFF   67584                  // 128*528
#define SM_B_SZ    67584
#define SM_LIST_OFF 202752                // 67584*3
#define SM_CNT_OFF  219136                // +128*32*4
#define SM_RMAX_OFF 219648
#define SM_TOTAL    220160

__device__ __forceinline__ unsigned fkey(float f) {
    unsigned u = __float_as_uint(f);
    return (u & 0x80000000u) ? ~u : (u | 0x80000000u);
}
__device__ __forceinline__ float fdec(unsigned k) {
    unsigned u = (k & 0x80000000u) ? (k & 0x7fffffffu) : ~k;
    return __uint_as_float(u);
}

#define CP_ASYNC16(dst, src) \
    asm volatile("cp.async.cg.shared.global [%0],[%1],16;\n" :: "r"(dst), "l"(src))

__global__ __launch_bounds__(256, 1) void screen_kernel() {
    extern __shared__ char sm[];
    const int tid  = threadIdx.x;
    const int lane = tid & 31;
    const int wid  = tid >> 5;
    const int warp_m = wid & 3;          // 4 m-strips of 32 rows
    const int warp_n = wid >> 2;         // 2 n-strips of 64 cands
    const int g  = lane >> 2;
    const int t4 = lane & 3;
    const int row0 = blockIdx.x * 128;

    int*      list   = (int*)(sm + SM_LIST_OFF);
    int*      cnt    = (int*)(sm + SM_CNT_OFF);
    unsigned* rowmax = (unsigned*)(sm + SM_RMAX_OFF);
    if (tid < 128) { cnt[tid] = 0; rowmax[tid] = 0u; }

    const unsigned smu = (unsigned)__cvta_generic_to_shared(sm);

    // ---- preload A tile (128x256 bf16) + B tile 0 ----
    const __nv_bfloat16* Ag = g_zb + (size_t)row0 * 256;
#pragma unroll
    for (int i = 0; i < 16; ++i) {
        int chunk = tid + 256 * i;           // 0..4095
        int row = chunk >> 5;
        int kof = (chunk & 31) * 8;
        CP_ASYNC16(smu + SM_A_OFF + row * A_STRIDE_B + kof * 2, Ag + row * 256 + kof);
    }
    {
        const __nv_bfloat16* Bg = g_cbb;
#pragma unroll
        for (int i = 0; i < 16; ++i) {
            int chunk = tid + 256 * i;
            int row = chunk >> 5;
            int kof = (chunk & 31) * 8;
            CP_ASYNC16(smu + SM_B_OFF + row * A_STRIDE_B + kof * 2, Bg + row * 256 + kof);
        }
    }
    asm volatile("cp.async.commit_group;\n");

    // ldmatrix lane addressing
    const int a_row = warp_m * 32 + (lane & 15);
    const unsigned a_base = smu + SM_A_OFF + a_row * A_STRIDE_B + (lane >> 4) * 16;
    const int b_row_in = (lane & 7) + ((lane >> 4) & 1) * 8;
    const int b_kof  = ((lane >> 3) & 1) * 16;
    const unsigned b_rowoff = (unsigned)((warp_n * 64 + b_row_in) * A_STRIDE_B + b_kof);

    for (int t = 0; t < 64; ++t) {
        // prefetch next B tile
        if (t + 1 < 64) {
            const __nv_bfloat16* Bg = g_cbb + (size_t)(t + 1) * 128 * 256;
            unsigned dstb = smu + SM_B_OFF + ((t + 1) & 1) * SM_B_SZ;
#pragma unroll
            for (int i = 0; i < 16; ++i) {
                int chunk = tid + 256 * i;
                int row = chunk >> 5;
                int kof = (chunk & 31) * 8;
                CP_ASYNC16(dstb + row * A_STRIDE_B + kof * 2, Bg + row * 256 + kof);
            }
            asm volatile("cp.async.commit_group;\n");
            asm volatile("cp.async.wait_group 1;\n");
        } else {
            asm volatile("cp.async.wait_group 0;\n");
        }
        __syncthreads();

        float acc[2][8][4];
#pragma unroll
        for (int mi = 0; mi < 2; ++mi)
#pragma unroll
            for (int ni = 0; ni < 8; ++ni)
#pragma unroll
                for (int e = 0; e < 4; ++e) acc[mi][ni][e] = 0.0f;

        const unsigned bbuf = smu + SM_B_OFF + (t & 1) * SM_B_SZ + b_rowoff;
#pragma unroll 4
        for (int ks = 0; ks < 16; ++ks) {
            unsigned a0[2][4];
#pragma unroll
            for (int mi = 0; mi < 2; ++mi) {
                unsigned addr = a_base + mi * 16 * A_STRIDE_B + ks * 32;
                asm volatile("ldmatrix.sync.aligned.m8n8.x4.shared.b16 {%0,%1,%2,%3},[%4];"
                             : "=r"(a0[mi][0]), "=r"(a0[mi][1]), "=r"(a0[mi][2]), "=r"(a0[mi][3])
                             : "r"(addr));
            }
            unsigned bfr[8][2];
#pragma unroll
            for (int nf4 = 0; nf4 < 4; ++nf4) {
                unsigned r0, r1, r2, r3;
                unsigned addr = bbuf + nf4 * 16 * A_STRIDE_B + ks * 32;
                asm volatile("ldmatrix.sync.aligned.m8n8.x4.shared.b16 {%0,%1,%2,%3},[%4];"
                             : "=r"(r0), "=r"(r1), "=r"(r2), "=r"(r3) : "r"(addr));
                bfr[nf4 * 2][0] = r0; bfr[nf4 * 2][1] = r1;
                bfr[nf4 * 2 + 1][0] = r2; bfr[nf4 * 2 + 1][1] = r3;
            }
#pragma unroll
            for (int mi = 0; mi < 2; ++mi)
#pragma unroll
                for (int ni = 0; ni < 8; ++ni) {
                    asm volatile(
                        "mma.sync.aligned.m16n8k16.row.col.f32.bf16.bf16.f32 "
                        "{%0,%1,%2,%3},{%4,%5,%6,%7},{%8,%9},{%0,%1,%2,%3};"
                        : "+f"(acc[mi][ni][0]), "+f"(acc[mi][ni][1]),
                          "+f"(acc[mi][ni][2]), "+f"(acc[mi][ni][3])
                        : "r"(a0[mi][0]), "r"(a0[mi][1]), "r"(a0[mi][2]), "r"(a0[mi][3]),
                          "r"(bfr[ni][0]), "r"(bfr[ni][1]));
                }
        }

        // ---- pass 1: per-row local max -> atomicMax on rowmax ----
        float m[4];
#pragma unroll
        for (int s = 0; s < 4; ++s) m[s] = -3.4e38f;
#pragma unroll
        for (int mi = 0; mi < 2; ++mi)
#pragma unroll
            for (int ni = 0; ni < 8; ++ni) {
                m[mi * 2]     = fmaxf(m[mi * 2],     fmaxf(acc[mi][ni][0], acc[mi][ni][1]));
                m[mi * 2 + 1] = fmaxf(m[mi * 2 + 1], fmaxf(acc[mi][ni][2], acc[mi][ni][3]));
            }
#pragma unroll
        for (int s = 0; s < 4; ++s) {
            int r = warp_m * 32 + (s >> 1) * 16 + (s & 1) * 8 + g;
            atomicMax(&rowmax[r], fkey(m[s]));
        }
        __syncthreads();

        // ---- pass 2: append candidates within margin of running max ----
        float th[4];
#pragma unroll
        for (int s = 0; s < 4; ++s) {
            int r = warp_m * 32 + (s >> 1) * 16 + (s & 1) * 8 + g;
            th[s] = fdec(rowmax[r]) - MARGIN_EZ;
        }
#pragma unroll
        for (int mi = 0; mi < 2; ++mi)
#pragma unroll
            for (int ni = 0; ni < 8; ++ni)
#pragma unroll
                for (int e = 0; e < 4; ++e) {
                    int s = mi * 2 + (e >> 1);
                    if (acc[mi][ni][e] > th[s]) {
                        int r = warp_m * 32 + mi * 16 + (e >> 1) * 8 + g;
                        int k = t * 128 + warp_n * 64 + ni * 8 + t4 * 2 + (e & 1);
                        int slot = atomicAdd(&cnt[r], 1);
                        if (slot < CAP) list[r * CAP + slot] = k;
                    }
                }
        __syncthreads();   // protects B-buffer reuse + list/rowmax coherence
    }

    // ---- flush lists ----
    if (tid < 128) g_cnt[row0 + tid] = cnt[tid];
    for (int i = tid; i < 128 * CAP; i += 256) g_cand[row0 * CAP + i] = list[i];
}

// ---------------------------------------------------------------------------
// exact recheck: 1 warp per row; serial-ascending fp32 fmaf dot (bit-identical
// to R1's accumulation order), lexicographic (d, idx) min.
// ---------------------------------------------------------------------------
__global__ void recheck_kernel(const float* __restrict__ z,
                               const float* __restrict__ cb)
{
    const int n = blockIdx.x;
    const int lane = threadIdx.x;
    const int b = n >> 10;
    const int r = n & 1023;
    __shared__ float zs[256];
#pragma unroll
    for (int t = 0; t < 8; ++t)
        zs[lane + 32 * t] = z[(size_t)b * 262144 + (size_t)(lane + 32 * t) * 1024 + r];
    __syncwarp();

    const float z2v = g_z2[n];
    const int cnt = g_cnt[n];
    unsigned long long key = ~0ull;

    if (cnt <= CAP) {
        if (lane < cnt) {
            int k = g_cand[n * CAP + lane];
            const float* cr = cb + (size_t)k * 256;
            float a = 0.0f;
#pragma unroll 16
            for (int c = 0; c < 256; ++c) a = fmaf(zs[c], cr[c], a);
            float s = z2v + g_e2[k];
            float d = s - 2.0f * a;
            key = ((unsigned long long)__float_as_uint(d) << 32) | (unsigned)k;
        }
    } else {
        for (int k = lane; k < K_CB; k += 32) {
            const float* cr = cb + (size_t)k * 256;
            float a = 0.0f;
#pragma unroll 16
            for (int c = 0; c < 256; ++c) a = fmaf(zs[c], cr[c], a);
            float s = z2v + g_e2[k];
            float d = s - 2.0f * a;
            unsigned long long kk = ((unsigned long long)__float_as_uint(d) << 32) | (unsigned)k;
            key = (kk < key) ? kk : key;
        }
    }
#pragma unroll
    for (int o = 16; o > 0; o >>= 1) {
        unsigned long long ok = __shfl_xor_sync(0xffffffffu, key, o);
        key = (ok < key) ? ok : key;
    }
    if (lane == 0) g_bestidx[n] = (int)(unsigned)(key & 0xffffffffu);
}

// ---------------------------------------------------------------------------
// epilogue (scrambled gather + loss partials) & finalize — unchanged from R1
// ---------------------------------------------------------------------------
__global__ void epilogue_kernel(const float* __restrict__ z,
                                const float* __restrict__ cb,
                                float* __restrict__ out, int out_size)
{
    int t = blockIdx.x * 256 + threadIdx.x;
    float diff2 = 0.0f;
    if (t < Z_ELEMS) {
        int c2 = t & 255;
        int w2 = (t >> 8) & 31;
        int h2 = (t >> 13) & 31;
        int b  = t >> 18;
        int n = b * 1024 + w2 * 32 + (c2 >> 3);
        int c = (c2 & 7) * 32 + h2;
        float v = cb[(size_t)g_bestidx[n] * C_DIM + c];
        if (t < out_size) out[t] = v;
        float zp = z[(size_t)b * 262144 + (size_t)c2 * 1024 + h2 * 32 + w2];
        float d = zp - v;
        diff2 = d * d;
    }
    __shared__ double sred[256];
    sred[threadIdx.x] = (double)diff2;
    __syncthreads();
#pragma unroll
    for (int s = 128; s > 0; s >>= 1) {
        if (threadIdx.x < s) sred[threadIdx.x] += sred[threadIdx.x + s];
        __syncthreads();
    }
    if (threadIdx.x == 0) g_losspart[blockIdx.x] = sred[0];
}

__global__ void finalize_kernel(float* __restrict__ out, int out_size)
{
    __shared__ double sred[256];
    double s = 0.0;
    for (int i = threadIdx.x; i < 16384; i += 256) s += g_losspart[i];
    sred[threadIdx.x] = s;
    __syncthreads();
#pragma unroll
    for (int st = 128; st > 0; st >>= 1) {
        if (threadIdx.x < st) sred[threadIdx.x] += sred[threadIdx.x + st];
        __syncthreads();
    }
    if (threadIdx.x == 0) {
        double m = sred[0] / (double)Z_ELEMS;
        float loss = (float)(m + 0.25 * m);
        if (OUT_LOSS_OFF < out_size) out[OUT_LOSS_OFF] = loss;
    }
    for (int i = threadIdx.x; i < N_ROWS; i += 256) {
        int o = OUT_IDX_OFF + i;
        if (o < out_size) out[o] = (float)g_bestidx[i];
    }
}

extern "C" void kernel_launch(void* const* d_in, const int* in_sizes, int n_in,
                              void* d_out, int out_size)
{
    const float* z  = (const float*)d_in[0];
    const float* cb = (const float*)d_in[1];
    float* out = (float*)d_out;

    cudaFuncSetAttribute(screen_kernel,
                         cudaFuncAttributeMaxDynamicSharedMemorySize, SM_TOTAL);

    convert_z_kernel<<<Z_ELEMS / 256, 256>>>(z);
    convert_cb_kernel<<<(K_CB * C_DIM) / 256, 256>>>(cb);
    z2_kernel<<<(N_ROWS * 32) / 256, 256>>>(z);
    e2_kernel<<<(K_CB * 32) / 256, 256>>>(cb);
    screen_kernel<<<N_ROWS / 128, 256, SM_TOTAL>>>();
    recheck_kernel<<<N_ROWS, 32>>>(z, cb);
    epilogue_kernel<<<Z_ELEMS / 256, 256>>>(z, cb, out, out_size);
    finalize_kernel<<<1, 256>>>(out, out_size);
}

// round 4
// speedup vs baseline: 2.8864x; 2.8864x over previous
#include <cuda_runtime.h>
#include <cuda_bf16.h>
#include <cstdint>

#define BATCH   16
#define C_DIM   256
#define HDIM    32
#define WDIM    32
#define N_ROWS  16384
#define K_CB    8192
#define Z_ELEMS 4194304
#define OUT_LOSS_OFF 4194304
#define OUT_IDX_OFF  4194305

#define CAP       32
#define MARGIN_EZ 2e-4f
#define CHUNKS    64            // 256 int8 = 64 packed int32 per row

// ---- static device scratch ----
__device__ __align__(16) int   g_qzT[CHUNKS][N_ROWS];   // z int8, chunk-major
__device__ __align__(16) int   g_cbT[CHUNKS][K_CB];     // codebook int8, chunk-major
__device__ float  g_z2[N_ROWS];
__device__ float  g_szinv[N_ROWS];   // 127/max|z_row|
__device__ float  g_e2[K_CB];
__device__ float  g_se[K_CB];        // max|e_k|/127
__device__ float  g_seinv[K_CB];     // 127/max|e_k|
__device__ int    g_cnt[N_ROWS];
__device__ int    g_cand[N_ROWS * CAP];
__device__ int    g_bestidx[N_ROWS];
__device__ double g_losspart[16384];

__device__ __forceinline__ unsigned fkey(float f) {
    unsigned u = __float_as_uint(f);
    return (u & 0x80000000u) ? ~u : (u | 0x80000000u);
}
__device__ __forceinline__ float fdec(unsigned k) {
    unsigned u = (k & 0x80000000u) ? (k & 0x7fffffffu) : ~k;
    return __uint_as_float(u);
}
__device__ __forceinline__ uint32_t smem_u32(const void* p) {
    uint32_t a;
    asm("{ .reg .u64 t; cvta.to.shared.u64 t, %1; cvt.u32.u64 %0, t; }" : "=r"(a) : "l"(p));
    return a;
}
#define CP_ASYNC16(dst, src) \
    asm volatile("cp.async.cg.shared.global [%0],[%1],16;\n" :: "r"(dst), "l"(src))
#define CP_COMMIT() asm volatile("cp.async.commit_group;\n")
#define CP_WAIT1()  asm volatile("cp.async.wait_group 1;\n")
#define CP_WAIT0()  asm volatile("cp.async.wait_group 0;\n")

// ---------------------------------------------------------------------------
// row stats: z2 (bit-identical to R1) + quantization scale
// ---------------------------------------------------------------------------
__global__ void rowstat_z_kernel(const float* __restrict__ z) {
    int warp = (blockIdx.x * blockDim.x + threadIdx.x) >> 5;
    int lane = threadIdx.x & 31;
    if (warp >= N_ROWS) return;
    int b = warp >> 10;
    int r = warp & 1023;
    const float* p = z + (size_t)b * 262144 + r;
    float s = 0.0f, mx = 0.0f;
#pragma unroll
    for (int t = 0; t < 8; ++t) {
        float v = p[(size_t)(lane + 32 * t) * 1024];
        s = fmaf(v, v, s);
        mx = fmaxf(mx, fabsf(v));
    }
#pragma unroll
    for (int o = 16; o > 0; o >>= 1) {
        s += __shfl_xor_sync(0xffffffffu, s, o);
        mx = fmaxf(mx, __shfl_xor_sync(0xffffffffu, mx, o));
    }
    if (lane == 0) {
        g_z2[warp] = s;
        mx = fmaxf(mx, 1e-20f);
        g_szinv[warp] = 127.0f / mx;
    }
}
__global__ void rowstat_e_kernel(const float* __restrict__ cb) {
    int warp = (blockIdx.x * blockDim.x + threadIdx.x) >> 5;
    int lane = threadIdx.x & 31;
    if (warp >= K_CB) return;
    const float* p = cb + (size_t)warp * C_DIM;
    float s = 0.0f, mx = 0.0f;
#pragma unroll
    for (int t = 0; t < 8; ++t) {
        float v = p[lane + 32 * t];
        s = fmaf(v, v, s);
        mx = fmaxf(mx, fabsf(v));
    }
#pragma unroll
    for (int o = 16; o > 0; o >>= 1) {
        s += __shfl_xor_sync(0xffffffffu, s, o);
        mx = fmaxf(mx, __shfl_xor_sync(0xffffffffu, mx, o));
    }
    if (lane == 0) {
        g_e2[warp] = s;
        mx = fmaxf(mx, 1e-20f);
        g_se[warp]    = mx * (1.0f / 127.0f);
        g_seinv[warp] = 127.0f / mx;
    }
}

// ---------------------------------------------------------------------------
// quantize + transpose to chunk-major
// ---------------------------------------------------------------------------
__device__ __forceinline__ int q8(float v, float inv) {
    int q = __float2int_rn(v * inv);
    q = max(-127, min(127, q));
    return q & 255;
}
__global__ void quant_z_kernel(const float* __restrict__ z) {
    int t = blockIdx.x * 256 + threadIdx.x;       // [0, 64*16384)
    int cc = t >> 14;
    int n  = t & 16383;
    int b = n >> 10;
    int r = n & 1023;
    const float* p = z + (size_t)b * 262144 + (size_t)(cc * 4) * 1024 + r;
    float inv = g_szinv[n];
    int w = q8(p[0], inv) | (q8(p[1024], inv) << 8) |
            (q8(p[2048], inv) << 16) | (q8(p[3072], inv) << 24);
    g_qzT[cc][n] = w;
}
__global__ void quant_cb_kernel(const float* __restrict__ cb) {
    int t = blockIdx.x * 256 + threadIdx.x;       // [0, 64*8192)
    int cc = t >> 13;
    int k  = t & 8191;
    float4 v = *(const float4*)(cb + (size_t)k * 256 + cc * 4);
    float inv = g_seinv[k];
    int w = q8(v.x, inv) | (q8(v.y, inv) << 8) |
            (q8(v.z, inv) << 16) | (q8(v.w, inv) << 24);
    g_cbT[cc][k] = w;
}

// ---------------------------------------------------------------------------
// DP4A screen: block = 128 rows x all 8192 candidates (64 tiles of 128).
// 256 threads, 8x8 microtile, 64 int32 chunks (=256 int8) per dot.
// Score u = se[k] * D (s_z>0 constant per row -> monotone); threshold in
// u-units with margin_u = MARGIN_EZ * szinv[row].
// ---------------------------------------------------------------------------
#define A_BYTES   32768u                 // 64 chunks x 128 rows x 4
#define B_BYTES   32768u                 // 64 chunks x 128 cands x 4
#define SE_BYTES  512u
#define DYN_SM    (A_BYTES + 2u * B_BYTES + 2u * SE_BYTES)   // 99328

__global__ __launch_bounds__(256, 1) void screen_dp4a_kernel() {
    extern __shared__ char dsm[];
    int*   As = (int*)dsm;                                   // [64][128]
    int*   Bs = (int*)(dsm + A_BYTES);                       // [2][64][128]
    float* Se = (float*)(dsm + A_BYTES + 2u * B_BYTES);      // [2][128]
    __shared__ unsigned s_rowmax[128];
    __shared__ int s_cnt[128];
    __shared__ int s_list[128 * CAP];

    const int tid = threadIdx.x;
    const int tx = tid & 15;
    const int ty = tid >> 4;
    const int row0 = blockIdx.x * 128;
    const unsigned smu = smem_u32(dsm);

    if (tid < 128) { s_cnt[tid] = 0; s_rowmax[tid] = 0u; }

    float margin_u[8];
#pragma unroll
    for (int i = 0; i < 8; ++i)
        margin_u[i] = MARGIN_EZ * g_szinv[row0 + ty * 8 + i];

    // preload A + B0 + Se0 (one group)
#pragma unroll
    for (int i = 0; i < 8; ++i) {
        int id = tid + 256 * i;          // 2048 16B slots
        int cc = id >> 5, u = id & 31;
        CP_ASYNC16(smu + cc * 512 + u * 16, &g_qzT[cc][row0 + u * 4]);
    }
#pragma unroll
    for (int i = 0; i < 8; ++i) {
        int id = tid + 256 * i;
        int cc = id >> 5, u = id & 31;
        CP_ASYNC16(smu + A_BYTES + cc * 512 + u * 16, &g_cbT[cc][u * 4]);
    }
    if (tid < 32) CP_ASYNC16(smu + A_BYTES + 2u * B_BYTES + tid * 16, (const char*)g_se + tid * 16);
    CP_COMMIT();

    for (int t = 0; t < 64; ++t) {
        const int buf = t & 1;
        // prefetch tile t+1 into buffer buf^1 (consumed two iters ago; all
        // threads passed the syncthreads at the end of iter t-1)
        if (t + 1 < 64) {
            const int k1 = (t + 1) * 128;
            unsigned dst = smu + A_BYTES + (unsigned)(buf ^ 1) * B_BYTES;
#pragma unroll
            for (int i = 0; i < 8; ++i) {
                int id = tid + 256 * i;
                int cc = id >> 5, u = id & 31;
                CP_ASYNC16(dst + cc * 512 + u * 16, &g_cbT[cc][k1 + u * 4]);
            }
            if (tid < 32)
                CP_ASYNC16(smu + A_BYTES + 2u * B_BYTES + (unsigned)(buf ^ 1) * SE_BYTES + tid * 16,
                           (const char*)(g_se + k1) + tid * 16);
            CP_COMMIT();
            CP_WAIT1();
        } else {
            CP_WAIT0();
        }
        __syncthreads();

        const int* Bt  = Bs + buf * (B_BYTES / 4);
        const float* St = Se + buf * 128;
        int acc[8][8];
#pragma unroll
        for (int i = 0; i < 8; ++i)
#pragma unroll
            for (int j = 0; j < 8; ++j) acc[i][j] = 0;

#pragma unroll 8
        for (int cc = 0; cc < 64; ++cc) {
            int a[8], b[8];
            *(int4*)&a[0] = *(const int4*)&As[cc * 128 + ty * 8];
            *(int4*)&a[4] = *(const int4*)&As[cc * 128 + ty * 8 + 4];
            *(int4*)&b[0] = *(const int4*)&Bt[cc * 128 + tx * 8];
            *(int4*)&b[4] = *(const int4*)&Bt[cc * 128 + tx * 8 + 4];
#pragma unroll
            for (int i = 0; i < 8; ++i)
#pragma unroll
                for (int j = 0; j < 8; ++j)
                    acc[i][j] = __dp4a(a[i], b[j], acc[i][j]);
        }

        // pass 1: running row max in u = se*D units
        float sev[8];
#pragma unroll
        for (int j = 0; j < 8; ++j) sev[j] = St[tx * 8 + j];
#pragma unroll
        for (int i = 0; i < 8; ++i) {
            float m = -3.4e38f;
#pragma unroll
            for (int j = 0; j < 8; ++j) m = fmaxf(m, sev[j] * (float)acc[i][j]);
            atomicMax(&s_rowmax[ty * 8 + i], fkey(m));
        }
        __syncthreads();

        // pass 2: append candidates within margin of running max
#pragma unroll
        for (int i = 0; i < 8; ++i) {
            const int r = ty * 8 + i;
            const float th = fdec(s_rowmax[r]) - margin_u[i];
#pragma unroll
            for (int j = 0; j < 8; ++j) {
                float v = sev[j] * (float)acc[i][j];
                if (v > th) {
                    int slot = atomicAdd(&s_cnt[r], 1);
                    if (slot < CAP) s_list[r * CAP + slot] = t * 128 + tx * 8 + j;
                }
            }
        }
        __syncthreads();
    }

    if (tid < 128) g_cnt[row0 + tid] = s_cnt[tid];
    for (int i = tid; i < 128 * CAP; i += 256) g_cand[row0 * CAP + i] = s_list[i];
}

// ---------------------------------------------------------------------------
// exact recheck: bit-identical fp32 path to R1 (serial-ascending fmaf),
// lexicographic (d, idx) min.
// ---------------------------------------------------------------------------
__global__ void recheck_kernel(const float* __restrict__ z,
                               const float* __restrict__ cb)
{
    const int n = blockIdx.x;
    const int lane = threadIdx.x;
    const int b = n >> 10;
    const int r = n & 1023;
    __shared__ float zs[256];
#pragma unroll
    for (int t = 0; t < 8; ++t)
        zs[lane + 32 * t] = z[(size_t)b * 262144 + (size_t)(lane + 32 * t) * 1024 + r];
    __syncwarp();

    const float z2v = g_z2[n];
    const int cnt = g_cnt[n];
    unsigned long long key = ~0ull;

    if (cnt <= CAP) {
        if (lane < cnt) {
            int k = g_cand[n * CAP + lane];
            const float* cr = cb + (size_t)k * 256;
            float a = 0.0f;
#pragma unroll 16
            for (int c = 0; c < 256; ++c) a = fmaf(zs[c], cr[c], a);
            float d = (z2v + g_e2[k]) - 2.0f * a;
            key = ((unsigned long long)__float_as_uint(d) << 32) | (unsigned)k;
        }
    } else {
        for (int k = lane; k < K_CB; k += 32) {
            const float* cr = cb + (size_t)k * 256;
            float a = 0.0f;
#pragma unroll 16
            for (int c = 0; c < 256; ++c) a = fmaf(zs[c], cr[c], a);
            float d = (z2v + g_e2[k]) - 2.0f * a;
            unsigned long long kk = ((unsigned long long)__float_as_uint(d) << 32) | (unsigned)k;
            key = (kk < key) ? kk : key;
        }
    }
#pragma unroll
    for (int o = 16; o > 0; o >>= 1) {
        unsigned long long ok = __shfl_xor_sync(0xffffffffu, key, o);
        key = (ok < key) ? ok : key;
    }
    if (lane == 0) g_bestidx[n] = (int)(unsigned)(key & 0xffffffffu);
}

// ---------------------------------------------------------------------------
// epilogue (scrambled gather per the reference's mislabeled unpack) + loss
// ---------------------------------------------------------------------------
__global__ void epilogue_kernel(const float* __restrict__ z,
                                const float* __restrict__ cb,
                                float* __restrict__ out, int out_size)
{
    int t = blockIdx.x * 256 + threadIdx.x;
    float diff2 = 0.0f;
    if (t < Z_ELEMS) {
        int c2 = t & 255;
        int w2 = (t >> 8) & 31;
        int h2 = (t >> 13) & 31;
        int b  = t >> 18;
        int n = b * 1024 + w2 * 32 + (c2 >> 3);
        int c = (c2 & 7) * 32 + h2;
        float v = cb[(size_t)g_bestidx[n] * C_DIM + c];
        if (t < out_size) out[t] = v;
        float zp = z[(size_t)b * 262144 + (size_t)c2 * 1024 + h2 * 32 + w2];
        float d = zp - v;
        diff2 = d * d;
    }
    __shared__ double sred[256];
    sred[threadIdx.x] = (double)diff2;
    __syncthreads();
#pragma unroll
    for (int s = 128; s > 0; s >>= 1) {
        if (threadIdx.x < s) sred[threadIdx.x] += sred[threadIdx.x + s];
        __syncthreads();
    }
    if (threadIdx.x == 0) g_losspart[blockIdx.x] = sred[0];
}

__global__ void finalize_kernel(float* __restrict__ out, int out_size)
{
    __shared__ double sred[256];
    double s = 0.0;
    for (int i = threadIdx.x; i < 16384; i += 256) s += g_losspart[i];
    sred[threadIdx.x] = s;
    __syncthreads();
#pragma unroll
    for (int st = 128; st > 0; st >>= 1) {
        if (threadIdx.x < st) sred[threadIdx.x] += sred[threadIdx.x + st];
        __syncthreads();
    }
    if (threadIdx.x == 0) {
        double m = sred[0] / (double)Z_ELEMS;
        float loss = (float)(m + 0.25 * m);
        if (OUT_LOSS_OFF < out_size) out[OUT_LOSS_OFF] = loss;
    }
    for (int i = threadIdx.x; i < N_ROWS; i += 256) {
        int o = OUT_IDX_OFF + i;
        if (o < out_size) out[o] = (float)g_bestidx[i];
    }
}

extern "C" void kernel_launch(void* const* d_in, const int* in_sizes, int n_in,
                              void* d_out, int out_size)
{
    const float* z  = (const float*)d_in[0];
    const float* cb = (const float*)d_in[1];
    float* out = (float*)d_out;

    cudaFuncSetAttribute(screen_dp4a_kernel,
                         cudaFuncAttributeMaxDynamicSharedMemorySize, DYN_SM);

    rowstat_z_kernel<<<(N_ROWS * 32) / 256, 256>>>(z);
    rowstat_e_kernel<<<(K_CB * 32) / 256, 256>>>(cb);
    quant_z_kernel<<<(CHUNKS * N_ROWS) / 256, 256>>>(z);
    quant_cb_kernel<<<(CHUNKS * K_CB) / 256, 256>>>(cb);
    screen_dp4a_kernel<<<N_ROWS / 128, 256, DYN_SM>>>();
    recheck_kernel<<<N_ROWS, 32>>>(z, cb);
    epilogue_kernel<<<Z_ELEMS / 256, 256>>>(z, cb, out, out_size);
    finalize_kernel<<<1, 256>>>(out, out_size);
}